// round 1
// baseline (speedup 1.0000x reference)
#include <cuda_runtime.h>
#include <math.h>

#define BB   4
#define CIN  64
#define HID  64
#define HH   64
#define WW   64
#define NN   9
#define DD   256
#define INCC 128
#define OUTC 256
#define HP   66
#define HW   4096
#define KTOT 1152   // INCC * NN

// ---- scratch (static device globals; no allocation allowed) ----
__device__ float g_xpad[BB * INCC * HP * HP];            // padded concat(input,h)  ~8.9MB
__device__ float g_wm1t[BB * DD * INCC];                 // [b][d][c]               0.5MB
__device__ float g_wm[(size_t)BB * OUTC * KTOT];         // [b][o][c*9+n]           4.7MB
__device__ float g_bm[BB * OUTC];
__device__ float g_off[BB * 18 * HW];                    // offset field            1.2MB
__device__ float g_xoff[(size_t)BB * KTOT * HW];         // sampled map             75.5MB
__device__ float g_comb[(size_t)BB * OUTC * HW];         // pre-gate activations    16.8MB

// ---------------------------------------------------------------
// 0) build zero-padded concat(input_tensor, h_cur): (b, 128, 66, 66)
__global__ void k_xpad(const float* __restrict__ inp, const float* __restrict__ hcur) {
    int idx = blockIdx.x * 256 + threadIdx.x;
    if (idx >= BB * INCC * HP * HP) return;
    int xy = idx % (HP * HP);
    int bc = idx / (HP * HP);
    int y = xy / HP, x = xy % HP;
    int c = bc % INCC, b = bc / INCC;
    float v = 0.f;
    if (y >= 1 && y <= HH && x >= 1 && x <= WW) {
        int pix = (y - 1) * WW + (x - 1);
        if (c < CIN) v = inp[((size_t)(b * CIN + c)) * HW + pix];
        else         v = hcur[((size_t)(b * HID + (c - CIN))) * HW + pix];
    }
    g_xpad[idx] = v;
}

// ---------------------------------------------------------------
// 1) wm1t[b][d][c] = sum_k meta[b][k] * w1_w[(c*D+d)][k] + w1_b[c*D+d]
__global__ void k_wm1(const float* __restrict__ meta, const float* __restrict__ w1w,
                      const float* __restrict__ w1b) {
    int d = blockIdx.x, b = blockIdx.y, c = threadIdx.x;   // 128 threads
    __shared__ float sm[DD];
    for (int k = threadIdx.x; k < DD; k += INCC) sm[k] = meta[b * DD + k];
    __syncthreads();
    const float4* row = (const float4*)(w1w + (size_t)(c * DD + d) * DD);
    float acc = 0.f;
#pragma unroll 8
    for (int k4 = 0; k4 < DD / 4; k4++) {
        float4 wv = row[k4];
        acc += wv.x * sm[k4 * 4 + 0] + wv.y * sm[k4 * 4 + 1]
             + wv.z * sm[k4 * 4 + 2] + wv.w * sm[k4 * 4 + 3];
    }
    g_wm1t[((size_t)b * DD + d) * INCC + c] = acc + w1b[c * DD + d];
}

// ---------------------------------------------------------------
// 2) wm[b][o][c][n] = sum_d wm1t[b][d][c] * w2_w[(o*9+n)][d] + w2_b[o*9+n]
__global__ void k_wm2(const float* __restrict__ w2w, const float* __restrict__ w2b) {
    int o = blockIdx.x, b = blockIdx.y, c = threadIdx.x;   // 128 threads
    __shared__ float sw[NN * DD];                          // 9KB
    for (int i = threadIdx.x; i < NN * DD; i += INCC)
        sw[i] = w2w[(size_t)o * NN * DD + i];              // sw[n*DD + d]
    __syncthreads();
    float acc[NN];
#pragma unroll
    for (int n = 0; n < NN; n++) acc[n] = 0.f;
    const float* a = g_wm1t + (size_t)b * DD * INCC + c;
#pragma unroll 4
    for (int d = 0; d < DD; d++) {
        float av = a[(size_t)d * INCC];
#pragma unroll
        for (int n = 0; n < NN; n++) acc[n] += av * sw[n * DD + d];
    }
    float* out = g_wm + (((size_t)(b * OUTC + o)) * INCC + c) * NN;
#pragma unroll
    for (int n = 0; n < NN; n++) out[n] = acc[n] + w2b[o * NN + n];
}

// ---------------------------------------------------------------
// 3) bm[b][o] = meta[b] . bl_w[o] + bl_b[o]
__global__ void k_bm(const float* __restrict__ meta, const float* __restrict__ blw,
                     const float* __restrict__ blb) {
    int b = blockIdx.x, o = threadIdx.x;                   // 256 threads
    __shared__ float sm[DD];
    for (int k = threadIdx.x; k < DD; k += OUTC) sm[k] = meta[b * DD + k];
    __syncthreads();
    float acc = 0.f;
#pragma unroll 4
    for (int d = 0; d < DD; d++) acc += sm[d] * blw[o * DD + d];
    g_bm[b * OUTC + o] = acc + blb[o];
}

// ---------------------------------------------------------------
// 4) offset = conv3x3(meta_info_offset) + bias   -> (b, 18, 64, 64)
__global__ void k_off(const float* __restrict__ mo, const float* __restrict__ pw,
                      const float* __restrict__ pb) {
    int idx = blockIdx.x * 256 + threadIdx.x;
    if (idx >= BB * 18 * HW) return;
    int hw = idx % HW;
    int j = (idx / HW) % 18;
    int b = idx / (18 * HW);
    int y = hw / WW, x = hw % WW;
    const float* in = mo + (size_t)b * HW;
    float acc = pb[j];
#pragma unroll
    for (int u = 0; u < 3; u++) {
        int yy = y + u - 1;
        if (yy < 0 || yy >= HH) continue;
#pragma unroll
        for (int v = 0; v < 3; v++) {
            int xx = x + v - 1;
            if (xx < 0 || xx >= WW) continue;
            acc += pw[j * 9 + u * 3 + v] * in[yy * WW + xx];
        }
    }
    g_off[idx] = acc;
}

// ---------------------------------------------------------------
// 5) deformable bilinear sampling -> xoff[b][c*9+n][hw]
__global__ void k_sample() {
    int hw = blockIdx.x * 256 + threadIdx.x;
    int bn = blockIdx.y;
    int n = bn % NN, b = bn / NN;
    int h = hw / WW, w = hw % WW;

    float ox = g_off[((size_t)(b * 18) + n) * HW + hw];
    float oy = g_off[((size_t)(b * 18) + 9 + n) * HW + hw];
    float px = (float)(h + 1) + (float)(n / 3 - 1) + ox;
    float py = (float)(w + 1) + (float)(n % 3 - 1) + oy;

    float fx = floorf(px), fy = floorf(py);
    float ltx = fminf(fmaxf(fx,        0.f), 65.f);
    float lty = fminf(fmaxf(fy,        0.f), 65.f);
    float rbx = fminf(fmaxf(fx + 1.f,  0.f), 65.f);
    float rby = fminf(fmaxf(fy + 1.f,  0.f), 65.f);
    float pcx = fminf(fmaxf(px,        0.f), 65.f);
    float pcy = fminf(fmaxf(py,        0.f), 65.f);

    float glt = (1.f + ltx - pcx) * (1.f + lty - pcy);
    float grb = (1.f - rbx + pcx) * (1.f - rby + pcy);
    float glb = (1.f + ltx - pcx) * (1.f - rby + pcy);
    float grt = (1.f - rbx + pcx) * (1.f + lty - pcy);

    int ilt = (int)ltx * HP + (int)lty;
    int irb = (int)rbx * HP + (int)rby;
    int ilb = (int)ltx * HP + (int)rby;
    int irt = (int)rbx * HP + (int)lty;

    const float* xp = g_xpad + (size_t)b * INCC * HP * HP;
    float* outp = g_xoff + ((size_t)b * KTOT + n) * HW + hw;
#pragma unroll 4
    for (int c = 0; c < INCC; c++) {
        const float* xc = xp + (size_t)c * HP * HP;
        float v = glt * xc[ilt] + grb * xc[irb] + glb * xc[ilb] + grt * xc[irt];
        outp[(size_t)c * NN * HW] = v;
    }
}

// ---------------------------------------------------------------
// 6) combined[b] (256x4096) = wm[b] (256x1152) @ xoff[b] (1152x4096) + bm[b]
#define BM 128
#define BN 128
#define BK 16
__global__ __launch_bounds__(256, 2) void k_gemm() {
    __shared__ float As[BK][BM];
    __shared__ float Bs[BK][BN];
    int b = blockIdx.z;
    int bm = blockIdx.y * BM, bn = blockIdx.x * BN;
    const float* A  = g_wm   + (size_t)b * OUTC * KTOT;   // 256 x 1152 row-major
    const float* Bm = g_xoff + (size_t)b * KTOT * HW;     // 1152 x 4096 row-major
    int t = threadIdx.x;
    int tx = t % 16, ty = t / 16;

    float acc[8][8];
#pragma unroll
    for (int i = 0; i < 8; i++)
#pragma unroll
        for (int j = 0; j < 8; j++) acc[i][j] = 0.f;

    int arow = t % 128;          // A tile row
    int akq  = (t / 128) * 2;    // which float4 chunk pair (0 or 2)
    int bc4  = t % 32;           // B tile float4 col
    int bkr  = t / 32;           // B tile k-row (0..7)

    for (int kk = 0; kk < KTOT; kk += BK) {
#pragma unroll
        for (int j = 0; j < 2; j++) {
            float4 av = *(const float4*)(A + (size_t)(bm + arow) * KTOT + kk + (akq + j) * 4);
            As[(akq + j) * 4 + 0][arow] = av.x;
            As[(akq + j) * 4 + 1][arow] = av.y;
            As[(akq + j) * 4 + 2][arow] = av.z;
            As[(akq + j) * 4 + 3][arow] = av.w;
            float4 bv = *(const float4*)(Bm + (size_t)(kk + bkr + j * 8) * HW + bn + bc4 * 4);
            *(float4*)&Bs[bkr + j * 8][bc4 * 4] = bv;
        }
        __syncthreads();
#pragma unroll
        for (int k = 0; k < BK; k++) {
            float af[8], bf[8];
#pragma unroll
            for (int i = 0; i < 8; i++) af[i] = As[k][ty * 8 + i];
#pragma unroll
            for (int j = 0; j < 8; j++) bf[j] = Bs[k][tx * 8 + j];
#pragma unroll
            for (int i = 0; i < 8; i++)
#pragma unroll
                for (int j = 0; j < 8; j++) acc[i][j] += af[i] * bf[j];
        }
        __syncthreads();
    }

#pragma unroll
    for (int i = 0; i < 8; i++) {
        int row = bm + ty * 8 + i;
        float bias = g_bm[b * OUTC + row];
        float* crow = g_comb + ((size_t)b * OUTC + row) * HW + bn + tx * 8;
#pragma unroll
        for (int j = 0; j < 8; j++) crow[j] = acc[i][j] + bias;
    }
}

// ---------------------------------------------------------------
// 7) LSTM gates + state update; out = [h_next | c_next]
__global__ void k_lstm(const float* __restrict__ ccur, float* __restrict__ out, int half) {
    int idx = blockIdx.x * 256 + threadIdx.x;
    if (idx >= BB * HID * HW) return;
    int hw = idx % HW;
    int c  = (idx / HW) % HID;
    int b  = idx / (HID * HW);
    const float* cb = g_comb + (size_t)b * OUTC * HW + hw;
    float ci = cb[(size_t)(c +   0) * HW];
    float cf = cb[(size_t)(c +  64) * HW];
    float co = cb[(size_t)(c + 128) * HW];
    float cg = cb[(size_t)(c + 192) * HW];
    float ig = 1.f / (1.f + expf(-ci));
    float fg = 1.f / (1.f + expf(-cf));
    float og = 1.f / (1.f + expf(-co));
    float gg = tanhf(cg);
    float cp = ccur[idx];
    float cn = fg * cp + ig * gg;
    float hn = og * tanhf(cn);
    out[idx] = hn;
    out[half + idx] = cn;
}

// ---------------------------------------------------------------
extern "C" void kernel_launch(void* const* d_in, const int* in_sizes, int n_in,
                              void* d_out, int out_size) {
    const float* input = (const float*)d_in[0];
    const float* hcur  = (const float*)d_in[1];
    const float* ccur  = (const float*)d_in[2];
    const float* meta  = (const float*)d_in[3];
    const float* mo    = (const float*)d_in[4];
    const float* w1w   = (const float*)d_in[5];
    const float* w1b   = (const float*)d_in[6];
    const float* w2w   = (const float*)d_in[7];
    const float* w2b   = (const float*)d_in[8];
    const float* blw   = (const float*)d_in[9];
    const float* blb   = (const float*)d_in[10];
    const float* pw    = (const float*)d_in[11];
    const float* pb    = (const float*)d_in[12];
    float* out = (float*)d_out;

    k_xpad<<<(BB * INCC * HP * HP + 255) / 256, 256>>>(input, hcur);
    k_wm1 <<<dim3(DD, BB), INCC>>>(meta, w1w, w1b);
    k_wm2 <<<dim3(OUTC, BB), INCC>>>(w2w, w2b);
    k_bm  <<<BB, OUTC>>>(meta, blw, blb);
    k_off <<<(BB * 18 * HW + 255) / 256, 256>>>(mo, pw, pb);
    k_sample<<<dim3(HW / 256, BB * NN), 256>>>();
    k_gemm<<<dim3(HW / BN, OUTC / BM, BB), 256>>>();
    k_lstm<<<(BB * HID * HW + 255) / 256, 256>>>(ccur, out, out_size / 2);
}

// round 4
// speedup vs baseline: 1.7201x; 1.7201x over previous
#include <cuda_runtime.h>
#include <cuda_bf16.h>
#include <cstdint>
#include <math.h>

#define BB   4
#define CIN  64
#define HID  64
#define HH   64
#define WW   64
#define NN   9
#define DD   256
#define INCC 128
#define OUTC 256
#define HP   66
#define HW   4096
#define KTOT 1152   // INCC * NN
#define KROW (KTOT * 2)   // bf16 hi|lo packed row length (elements)

// ---- scratch (static device globals; no allocation allowed) ----
__device__ float g_xpad[BB * INCC * HP * HP];            // padded concat(input,h)
__device__ float g_wm1t[BB * DD * INCC];                 // [b][d][c]
__device__ __nv_bfloat16 g_wm2[(size_t)BB * OUTC * KROW];    // A hi|lo packed
__device__ float g_bm[BB * OUTC];
__device__ float g_off[BB * 18 * HW];                    // offset field
__device__ __nv_bfloat16 g_xoffT2[(size_t)BB * HW * KROW];   // B hi|lo packed
__device__ float g_comb[(size_t)BB * OUTC * HW];         // pre-gate activations

// ============================================================
__device__ __forceinline__ uint32_t smem_u32(const void* p) {
    uint32_t a;
    asm("{ .reg .u64 t; cvta.to.shared.u64 t, %1; cvt.u32.u64 %0, t; }" : "=r"(a) : "l"(p));
    return a;
}
#define CP_ASYNC16(dst, src) \
    asm volatile("cp.async.cg.shared.global [%0], [%1], 16;" :: "r"(dst), "l"(src))
#define CP_COMMIT() asm volatile("cp.async.commit_group;" ::: "memory")

__device__ __forceinline__ void mma_bf16(float* c, const uint32_t* a, const uint32_t* b) {
    asm volatile(
        "mma.sync.aligned.m16n8k16.row.col.f32.bf16.bf16.f32 "
        "{%0,%1,%2,%3}, {%4,%5,%6,%7}, {%8,%9}, {%0,%1,%2,%3};"
        : "+f"(c[0]), "+f"(c[1]), "+f"(c[2]), "+f"(c[3])
        : "r"(a[0]), "r"(a[1]), "r"(a[2]), "r"(a[3]), "r"(b[0]), "r"(b[1]));
}

// write one fp32 value as packed hi/lo bf16 at k within a KROW row
__device__ __forceinline__ void store_hilo(__nv_bfloat16* rowbase, int k, float v) {
    __nv_bfloat16 hi = __float2bfloat16(v);
    float lo = v - __bfloat162float(hi);
    size_t base = (size_t)(k >> 5) * 64 + (k & 31);
    rowbase[base]      = hi;
    rowbase[base + 32] = __float2bfloat16(lo);
}

// ---------------------------------------------------------------
// 0) zero-padded concat(input, h_cur): (b, 128, 66, 66)
__global__ void k_xpad(const float* __restrict__ inp, const float* __restrict__ hcur) {
    int idx = blockIdx.x * 256 + threadIdx.x;
    if (idx >= BB * INCC * HP * HP) return;
    int xy = idx % (HP * HP);
    int bc = idx / (HP * HP);
    int y = xy / HP, x = xy % HP;
    int c = bc % INCC, b = bc / INCC;
    float v = 0.f;
    if (y >= 1 && y <= HH && x >= 1 && x <= WW) {
        int pix = (y - 1) * WW + (x - 1);
        if (c < CIN) v = inp[((size_t)(b * CIN + c)) * HW + pix];
        else         v = hcur[((size_t)(b * HID + (c - CIN))) * HW + pix];
    }
    g_xpad[idx] = v;
}

// ---------------------------------------------------------------
// 1) wm1t[b][d][c] = meta[b] . w1_w[c*D+d] + w1_b[c*D+d]   (warp-per-output)
__global__ void k_wm1(const float* __restrict__ meta, const float* __restrict__ w1w,
                      const float* __restrict__ w1b) {
    int d = blockIdx.x, b = blockIdx.y;
    int wid = threadIdx.x >> 5, lid = threadIdx.x & 31;
    __shared__ float sm[DD];
    for (int k = threadIdx.x; k < DD; k += 128) sm[k] = meta[b * DD + k];
    __syncthreads();
#pragma unroll 4
    for (int j = 0; j < 32; j++) {
        int c = wid * 32 + j;
        const float4* row = (const float4*)(w1w + (size_t)(c * DD + d) * DD);
        float acc = 0.f;
#pragma unroll
        for (int q = 0; q < 2; q++) {
            int i4 = lid + 32 * q;
            float4 v = row[i4];
            acc += v.x * sm[i4 * 4] + v.y * sm[i4 * 4 + 1]
                 + v.z * sm[i4 * 4 + 2] + v.w * sm[i4 * 4 + 3];
        }
#pragma unroll
        for (int off = 16; off > 0; off >>= 1)
            acc += __shfl_down_sync(0xffffffffu, acc, off);
        if (lid == 0) g_wm1t[((size_t)b * DD + d) * INCC + c] = acc + w1b[c * DD + d];
    }
}

// ---------------------------------------------------------------
// 2) wm[b][o][c*9+n] = sum_d wm1t[b][d][c] * w2_w[(o*9+n)][d] + w2_b  -> hi/lo bf16
__global__ void k_wm2(const float* __restrict__ w2w, const float* __restrict__ w2b) {
    int o = blockIdx.x, b = blockIdx.y, c = threadIdx.x;   // 128 threads
    __shared__ float sw[NN * DD];
    for (int i = threadIdx.x; i < NN * DD; i += INCC)
        sw[i] = w2w[(size_t)o * NN * DD + i];
    __syncthreads();
    float acc[NN];
#pragma unroll
    for (int n = 0; n < NN; n++) acc[n] = 0.f;
    const float* a = g_wm1t + (size_t)b * DD * INCC + c;
#pragma unroll 4
    for (int d = 0; d < DD; d++) {
        float av = a[(size_t)d * INCC];
#pragma unroll
        for (int n = 0; n < NN; n++) acc[n] += av * sw[n * DD + d];
    }
    __nv_bfloat16* rowb = g_wm2 + (size_t)(b * OUTC + o) * KROW;
#pragma unroll
    for (int n = 0; n < NN; n++)
        store_hilo(rowb, c * NN + n, acc[n] + w2b[o * NN + n]);
}

// ---------------------------------------------------------------
// 3) bm[b][o] = meta[b] . bl_w[o] + bl_b[o]  (warp-per-output)
__global__ void k_bm(const float* __restrict__ meta, const float* __restrict__ blw,
                     const float* __restrict__ blb) {
    int b = blockIdx.y;
    int wid = threadIdx.x >> 5, lid = threadIdx.x & 31;
    int o = blockIdx.x * 8 + wid;
    __shared__ float sm[DD];
    for (int k = threadIdx.x; k < DD; k += 256) sm[k] = meta[b * DD + k];
    __syncthreads();
    const float4* row = (const float4*)(blw + (size_t)o * DD);
    float acc = 0.f;
#pragma unroll
    for (int q = 0; q < 2; q++) {
        int i4 = lid + 32 * q;
        float4 v = row[i4];
        acc += v.x * sm[i4 * 4] + v.y * sm[i4 * 4 + 1]
             + v.z * sm[i4 * 4 + 2] + v.w * sm[i4 * 4 + 3];
    }
#pragma unroll
    for (int off = 16; off > 0; off >>= 1)
        acc += __shfl_down_sync(0xffffffffu, acc, off);
    if (lid == 0) g_bm[b * OUTC + o] = acc + blb[o];
}

// ---------------------------------------------------------------
// 4) offset = conv3x3(meta_info_offset) + bias -> (b, 18, 64, 64)
__global__ void k_off(const float* __restrict__ mo, const float* __restrict__ pw,
                      const float* __restrict__ pb) {
    int idx = blockIdx.x * 256 + threadIdx.x;
    if (idx >= BB * 18 * HW) return;
    int hw = idx % HW;
    int j = (idx / HW) % 18;
    int b = idx / (18 * HW);
    int y = hw / WW, x = hw % WW;
    const float* in = mo + (size_t)b * HW;
    float acc = pb[j];
#pragma unroll
    for (int u = 0; u < 3; u++) {
        int yy = y + u - 1;
        if (yy < 0 || yy >= HH) continue;
#pragma unroll
        for (int v = 0; v < 3; v++) {
            int xx = x + v - 1;
            if (xx < 0 || xx >= WW) continue;
            acc += pw[j * 9 + u * 3 + v] * in[yy * WW + xx];
        }
    }
    g_off[idx] = acc;
}

// ---------------------------------------------------------------
// 5) deformable bilinear sampling -> g_xoffT2[b][hw] rows (hi/lo bf16 packed)
__global__ void k_sample2() {
    int wid = threadIdx.x >> 5, lid = threadIdx.x & 31;
    int b = blockIdx.y;
    int hw = blockIdx.x * 8 + wid;
    int h = hw >> 6, w = hw & 63;
    __shared__ float s_w[8][NN][4];
    __shared__ int   s_i[8][NN][4];
    if (lid < NN) {
        int n = lid;
        float ox = g_off[((size_t)(b * 18) + n) * HW + hw];
        float oy = g_off[((size_t)(b * 18) + 9 + n) * HW + hw];
        float px = (float)(h + 1) + (float)(n / 3 - 1) + ox;
        float py = (float)(w + 1) + (float)(n % 3 - 1) + oy;
        float fx = floorf(px), fy = floorf(py);
        float ltx = fminf(fmaxf(fx,       0.f), 65.f);
        float lty = fminf(fmaxf(fy,       0.f), 65.f);
        float rbx = fminf(fmaxf(fx + 1.f, 0.f), 65.f);
        float rby = fminf(fmaxf(fy + 1.f, 0.f), 65.f);
        float pcx = fminf(fmaxf(px,       0.f), 65.f);
        float pcy = fminf(fmaxf(py,       0.f), 65.f);
        s_w[wid][n][0] = (1.f + ltx - pcx) * (1.f + lty - pcy);  // lt
        s_w[wid][n][1] = (1.f - rbx + pcx) * (1.f - rby + pcy);  // rb
        s_w[wid][n][2] = (1.f + ltx - pcx) * (1.f - rby + pcy);  // lb
        s_w[wid][n][3] = (1.f - rbx + pcx) * (1.f + lty - pcy);  // rt
        s_i[wid][n][0] = (int)ltx * HP + (int)lty;
        s_i[wid][n][1] = (int)rbx * HP + (int)rby;
        s_i[wid][n][2] = (int)ltx * HP + (int)rby;
        s_i[wid][n][3] = (int)rbx * HP + (int)lty;
    }
    __syncwarp();
    const float* xp = g_xpad + (size_t)b * INCC * HP * HP;
    __nv_bfloat16* orow = g_xoffT2 + ((size_t)(b * HW) + hw) * KROW;
#pragma unroll 4
    for (int i = 0; i < 36; i++) {
        int k = i * 32 + lid;
        int c = k / NN;
        int n = k - c * NN;
        const float* xc = xp + (size_t)c * (HP * HP);
        float v = s_w[wid][n][0] * xc[s_i[wid][n][0]]
                + s_w[wid][n][1] * xc[s_i[wid][n][1]]
                + s_w[wid][n][2] * xc[s_i[wid][n][2]]
                + s_w[wid][n][3] * xc[s_i[wid][n][3]];
        __nv_bfloat16 hi = __float2bfloat16(v);
        float lo = v - __bfloat162float(hi);
        orow[i * 64 + lid]      = hi;
        orow[i * 64 + 32 + lid] = __float2bfloat16(lo);
    }
}

// ---------------------------------------------------------------
// 6) bf16x3 mma.sync GEMM: comb[b](256x4096) = wm[b](256x1152) @ xoffT[b]^T + bm
//    SMEM tile row: 128B = [32 hi bf16 | 32 lo bf16], XOR-16B swizzled
#define GBM 128
#define GBN 128
#define GBK 32
#define GSTAGE_BYTES 32768           // A 16KB + B 16KB
#define GSMEM (3 * GSTAGE_BYTES)
#define GNK (KTOT / GBK)             // 36

#define LDFRAG(base, r, ch, t4) \
    (*(const uint32_t*)((base) + (r) * 128 + ((((ch)) ^ ((r) & 7)) << 4) + 4 * (t4)))

__global__ __launch_bounds__(256) void k_gemm_mma() {
    extern __shared__ char smem[];
    int t = threadIdx.x, lane = t & 31, wid = t >> 5;
    int warp_m = wid & 3, warp_n = wid >> 2;
    int b = blockIdx.z;
    const __nv_bfloat16* Ab = g_wm2    + (size_t)(b * OUTC + blockIdx.y * GBM) * KROW;
    const __nv_bfloat16* Bb = g_xoffT2 + ((size_t)(b * HW) + blockIdx.x * GBN) * KROW;
    uint32_t sbase = smem_u32(smem);

    float acc[2][8][4];
#pragma unroll
    for (int i = 0; i < 2; i++)
#pragma unroll
        for (int j = 0; j < 8; j++)
#pragma unroll
            for (int q = 0; q < 4; q++) acc[i][j][q] = 0.f;

#define LOAD_STAGE(kt, s) do {                                                     \
    const __nv_bfloat16* A0 = Ab + (kt) * 64;                                      \
    const __nv_bfloat16* B0 = Bb + (kt) * 64;                                      \
    uint32_t sA = sbase + (s) * GSTAGE_BYTES;                                      \
    uint32_t sB = sA + 16384;                                                      \
    _Pragma("unroll")                                                              \
    for (int i = 0; i < 4; i++) {                                                  \
        int idx = i * 256 + t, row = idx >> 3, q = idx & 7;                        \
        CP_ASYNC16(sA + row * 128 + ((q ^ (row & 7)) << 4),                        \
                   A0 + (size_t)row * KROW + q * 8);                               \
    }                                                                              \
    _Pragma("unroll")                                                              \
    for (int i = 0; i < 4; i++) {                                                  \
        int idx = i * 256 + t, row = idx >> 3, q = idx & 7;                        \
        CP_ASYNC16(sB + row * 128 + ((q ^ (row & 7)) << 4),                        \
                   B0 + (size_t)row * KROW + q * 8);                               \
    }                                                                              \
} while (0)

    LOAD_STAGE(0, 0); CP_COMMIT();
    LOAD_STAGE(1, 1); CP_COMMIT();

    int g = lane >> 2, t4 = lane & 3;
    for (int kt = 0; kt < GNK; kt++) {
        asm volatile("cp.async.wait_group 1;" ::: "memory");
        __syncthreads();
        if (kt + 2 < GNK) { LOAD_STAGE(kt + 2, (kt + 2) % 3); }
        CP_COMMIT();
        const char* sA = smem + (kt % 3) * GSTAGE_BYTES;
        const char* sB = sA + 16384;
#pragma unroll
        for (int ks = 0; ks < 2; ks++) {
            int ch = ks * 2;                        // hi chunks: ch, ch+1; lo: +4
            uint32_t ah[2][4], al[2][4];
#pragma unroll
            for (int tm = 0; tm < 2; tm++) {
                int r0 = warp_m * 32 + tm * 16 + g, r1 = r0 + 8;
                ah[tm][0] = LDFRAG(sA, r0, ch,     t4);
                ah[tm][1] = LDFRAG(sA, r1, ch,     t4);
                ah[tm][2] = LDFRAG(sA, r0, ch + 1, t4);
                ah[tm][3] = LDFRAG(sA, r1, ch + 1, t4);
                al[tm][0] = LDFRAG(sA, r0, ch + 4, t4);
                al[tm][1] = LDFRAG(sA, r1, ch + 4, t4);
                al[tm][2] = LDFRAG(sA, r0, ch + 5, t4);
                al[tm][3] = LDFRAG(sA, r1, ch + 5, t4);
            }
            uint32_t bh[8][2], bl[8][2];
#pragma unroll
            for (int tn = 0; tn < 8; tn++) {
                int n = warp_n * 64 + tn * 8 + g;
                bh[tn][0] = LDFRAG(sB, n, ch,     t4);
                bh[tn][1] = LDFRAG(sB, n, ch + 1, t4);
                bl[tn][0] = LDFRAG(sB, n, ch + 4, t4);
                bl[tn][1] = LDFRAG(sB, n, ch + 5, t4);
            }
#pragma unroll
            for (int tm = 0; tm < 2; tm++)
#pragma unroll
                for (int tn = 0; tn < 8; tn++) {
                    mma_bf16(acc[tm][tn], ah[tm], bh[tn]);
                    mma_bf16(acc[tm][tn], ah[tm], bl[tn]);
                    mma_bf16(acc[tm][tn], al[tm], bh[tn]);
                }
        }
        __syncthreads();
    }

    // epilogue: add bias, write g_comb
    int c2 = t4 * 2;
#pragma unroll
    for (int tm = 0; tm < 2; tm++) {
        int row0 = blockIdx.y * GBM + warp_m * 32 + tm * 16 + g;
        float bias0 = g_bm[b * OUTC + row0];
        float bias1 = g_bm[b * OUTC + row0 + 8];
#pragma unroll
        for (int tn = 0; tn < 8; tn++) {
            int col = blockIdx.x * GBN + warp_n * 64 + tn * 8 + c2;
            float2 v0 = { acc[tm][tn][0] + bias0, acc[tm][tn][1] + bias0 };
            float2 v1 = { acc[tm][tn][2] + bias1, acc[tm][tn][3] + bias1 };
            *(float2*)(g_comb + ((size_t)(b * OUTC) + row0) * HW + col) = v0;
            *(float2*)(g_comb + ((size_t)(b * OUTC) + row0 + 8) * HW + col) = v1;
        }
    }
}

// ---------------------------------------------------------------
// 7) LSTM gates + state update; out = [h_next | c_next]
__global__ void k_lstm(const float* __restrict__ ccur, float* __restrict__ out, int half) {
    int idx = blockIdx.x * 256 + threadIdx.x;
    if (idx >= BB * HID * HW) return;
    int hw = idx % HW;
    int c  = (idx / HW) % HID;
    int b  = idx / (HID * HW);
    const float* cb = g_comb + (size_t)b * OUTC * HW + hw;
    float ci = cb[(size_t)(c +   0) * HW];
    float cf = cb[(size_t)(c +  64) * HW];
    float co = cb[(size_t)(c + 128) * HW];
    float cg = cb[(size_t)(c + 192) * HW];
    float ig = 1.f / (1.f + expf(-ci));
    float fg = 1.f / (1.f + expf(-cf));
    float og = 1.f / (1.f + expf(-co));
    float gg = tanhf(cg);
    float cp = ccur[idx];
    float cn = fg * cp + ig * gg;
    float hn = og * tanhf(cn);
    out[idx] = hn;
    out[half + idx] = cn;
}

// ---------------------------------------------------------------
extern "C" void kernel_launch(void* const* d_in, const int* in_sizes, int n_in,
                              void* d_out, int out_size) {
    const float* input = (const float*)d_in[0];
    const float* hcur  = (const float*)d_in[1];
    const float* ccur  = (const float*)d_in[2];
    const float* meta  = (const float*)d_in[3];
    const float* mo    = (const float*)d_in[4];
    const float* w1w   = (const float*)d_in[5];
    const float* w1b   = (const float*)d_in[6];
    const float* w2w   = (const float*)d_in[7];
    const float* w2b   = (const float*)d_in[8];
    const float* blw   = (const float*)d_in[9];
    const float* blb   = (const float*)d_in[10];
    const float* pw    = (const float*)d_in[11];
    const float* pb    = (const float*)d_in[12];
    float* out = (float*)d_out;

    static int smem_set = 0;
    if (!smem_set) {
        cudaFuncSetAttribute(k_gemm_mma, cudaFuncAttributeMaxDynamicSharedMemorySize, GSMEM);
        smem_set = 1;
    }

    k_xpad<<<(BB * INCC * HP * HP + 255) / 256, 256>>>(input, hcur);
    k_wm1 <<<dim3(DD, BB), 128>>>(meta, w1w, w1b);
    k_wm2 <<<dim3(OUTC, BB), INCC>>>(w2w, w2b);
    k_bm  <<<dim3(OUTC / 8, BB), 256>>>(meta, blw, blb);
    k_off <<<(BB * 18 * HW + 255) / 256, 256>>>(mo, pw, pb);
    k_sample2<<<dim3(HW / 8, BB), 256>>>();
    k_gemm_mma<<<dim3(HW / GBN, OUTC / GBM, BB), 256, GSMEM>>>();
    k_lstm<<<(BB * HID * HW + 255) / 256, 256>>>(ccur, out, out_size / 2);
}